// round 1
// baseline (speedup 1.0000x reference)
#include <cuda_runtime.h>

#define Dm 128
#define Hm 256
#define NB 16
#define TTOK 8192
#define NCH 1024
#define ROWS 16384   /* NB*NCH */
#define NTOK 131072  /* NB*TTOK */
#define EPSf 1e-5f

// ---- scratch (device globals; no allocation) ----
__device__ float g_local[NTOK * Dm];   // 64 MB
__device__ float g_hA[ROWS * Dm];      // 8 MB
__device__ float g_hB[ROWS * Dm];      // 8 MB
__device__ float g_proj[ROWS * Hm];    // 16 MB  [row][0:128]=self proj, [128:256]=nbr proj
__device__ float g_bcb[ROWS * Dm];     // 8 MB

__device__ __forceinline__ float wsum(float v) {
#pragma unroll
    for (int o = 16; o; o >>= 1) v += __shfl_xor_sync(0xffffffffu, v, o);
    return v;
}
__device__ __forceinline__ float gelu_f(float x) { return x * normcdff(x); }

// ============================================================
// K1: local = h + MLP2(LN(h)); h = emb[x] + pos[t%8]
// 32 tokens / block, 256 threads
// ============================================================
__global__ __launch_bounds__(256) void k_local(
    const int* __restrict__ x, const float* __restrict__ emb, const float* __restrict__ pos,
    const float* __restrict__ lw1, const float* __restrict__ lb1,
    const float* __restrict__ lw2, const float* __restrict__ lb2,
    const float* __restrict__ lng, const float* __restrict__ lnb)
{
    __shared__ float s_xln[32][Dm];   // 16 KB
    __shared__ float s_hid[32][Hm];   // 32 KB
    const int tid = threadIdx.x;
    const int wq = tid >> 5, lane = tid & 31;
    const int gt0 = blockIdx.x * 32;

    // phase 1: warp-per-token load + LN
#pragma unroll
    for (int tt = 0; tt < 4; ++tt) {
        const int tl = wq * 4 + tt;
        const int gt = gt0 + tl;
        const int xt = x[gt];
        const int cp = gt & 7;
        const float4 e = *(const float4*)(emb + xt * Dm + lane * 4);
        const float4 p = *(const float4*)(pos + cp * Dm + lane * 4);
        float h0 = e.x + p.x, h1 = e.y + p.y, h2 = e.z + p.z, h3 = e.w + p.w;
        const float mu = wsum(h0 + h1 + h2 + h3) * (1.0f / Dm);
        const float a0 = h0 - mu, a1 = h1 - mu, a2 = h2 - mu, a3 = h3 - mu;
        const float var = wsum(a0 * a0 + a1 * a1 + a2 * a2 + a3 * a3) * (1.0f / Dm);
        const float rs = rsqrtf(var + EPSf);
        const int dd = lane * 4;
        s_xln[tl][dd + 0] = a0 * rs * lng[dd + 0] + lnb[dd + 0];
        s_xln[tl][dd + 1] = a1 * rs * lng[dd + 1] + lnb[dd + 1];
        s_xln[tl][dd + 2] = a2 * rs * lng[dd + 2] + lnb[dd + 2];
        s_xln[tl][dd + 3] = a3 * rs * lng[dd + 3] + lnb[dd + 3];
    }
    __syncthreads();

    // phase 2: hidden[t][k] = gelu(xln[t] . lw1[:,k] + b1[k]) for k = tid
    {
        const int k = tid;
        float acc[32];
        const float bb = lb1[k];
#pragma unroll
        for (int t = 0; t < 32; ++t) acc[t] = bb;
#pragma unroll 4
        for (int d = 0; d < Dm; ++d) {
            const float w = lw1[d * Hm + k];
#pragma unroll
            for (int t = 0; t < 32; ++t) acc[t] += s_xln[t][d] * w;
        }
#pragma unroll
        for (int t = 0; t < 32; ++t) s_hid[t][k] = gelu_f(acc[t]);
    }
    __syncthreads();

    // phase 3: out[t][d] = h[t][d] + hid[t] . lw2[:,d] + b2[d]
    {
        const int hf = tid >> 7, d = tid & 127;
        const int tb = hf * 16;
        float acc[16];
        const float bb = lb2[d];
#pragma unroll
        for (int t = 0; t < 16; ++t) acc[t] = bb;
#pragma unroll 4
        for (int k = 0; k < Hm; ++k) {
            const float w = lw2[k * Dm + d];
#pragma unroll
            for (int t = 0; t < 16; ++t) acc[t] += s_hid[tb + t][k] * w;
        }
#pragma unroll
        for (int t = 0; t < 16; ++t) {
            const int gt = gt0 + tb + t;
            const int xt = x[gt];
            const float h = emb[xt * Dm + d] + pos[(gt & 7) * Dm + d];
            g_local[gt * Dm + d] = h + acc[t];
        }
    }
}

// ============================================================
// K2: summ = mean(local over chunk) @ pool_w + pool_b  -> g_hA
// 32 chunks / block
// ============================================================
__global__ __launch_bounds__(256) void k_pool(
    const float* __restrict__ pw, const float* __restrict__ pb)
{
    __shared__ float s_m[32][Dm];
    const int tid = threadIdx.x;
    const int gc0 = blockIdx.x * 32;
#pragma unroll
    for (int it = 0; it < 16; ++it) {
        const int idx = tid + it * 256;
        const int c = idx >> 7, d = idx & 127;
        const float* src = g_local + ((gc0 + c) * 8) * Dm + d;
        float s = 0.f;
#pragma unroll
        for (int j = 0; j < 8; ++j) s += src[j * Dm];
        s_m[c][d] = s * 0.125f;
    }
    __syncthreads();
    const int hf = tid >> 7, j = tid & 127;
    const int cb = hf * 16;
    float acc[16];
    const float bb = pb[j];
#pragma unroll
    for (int i = 0; i < 16; ++i) acc[i] = bb;
#pragma unroll 4
    for (int k = 0; k < Dm; ++k) {
        const float w = pw[k * Dm + j];
#pragma unroll
        for (int i = 0; i < 16; ++i) acc[i] += s_m[cb + i][k] * w;
    }
#pragma unroll
    for (int i = 0; i < 16; ++i) g_hA[(gc0 + cb + i) * Dm + j] = acc[i];
}

// ============================================================
// K3a: proj[row][k] : k<128 -> hmsg . msg_w1[0:128,k] (self half)
//                     k>=128 -> hmsg . msg_w1[128:256,k-128] (nbr half)
// ============================================================
__global__ __launch_bounds__(256) void k_proj(int useA, const float* __restrict__ mw1)
{
    const float* __restrict__ hin = useA ? g_hA : g_hB;
    __shared__ float s_r[32][Dm];
    const int tid = threadIdx.x;
    const int r0 = blockIdx.x * 32;
#pragma unroll
    for (int it = 0; it < 16; ++it) {
        const int idx = tid + it * 256;
        s_r[idx >> 7][idx & 127] = hin[r0 * Dm + idx];
    }
    __syncthreads();
    const int k = tid;
    const float* wp = mw1 + ((k < 128) ? k : (128 * Dm + (k - 128)));
    float acc[32];
#pragma unroll
    for (int r = 0; r < 32; ++r) acc[r] = 0.f;
#pragma unroll 4
    for (int d = 0; d < Dm; ++d) {
        const float w = wp[d * Dm];
#pragma unroll
        for (int r = 0; r < 32; ++r) acc[r] += s_r[r][d] * w;
    }
#pragma unroll
    for (int r = 0; r < 32; ++r) g_proj[(r0 + r) * Hm + k] = acc[r];
}

// ============================================================
// K3b: hsum -> agg -> upd MLP -> hmsg' = LN(hmsg + upd)
// 16 rows / block
// ============================================================
__global__ __launch_bounds__(256) void k_msg(
    int useA,
    const float* __restrict__ mb1, const float* __restrict__ mw2, const float* __restrict__ mb2,
    const float* __restrict__ uw1, const float* __restrict__ ub1,
    const float* __restrict__ uw2, const float* __restrict__ ub2,
    const float* __restrict__ lg, const float* __restrict__ lb)
{
    const float* __restrict__ hin = useA ? g_hA : g_hB;
    float* __restrict__ hout = useA ? g_hB : g_hA;
    __shared__ float s_hm[16][Dm];
    __shared__ float s_hs[16][Dm];
    __shared__ float s_ag[16][Dm];
    __shared__ float s_uh[16][Dm];
    const int tid = threadIdx.x;
    const int r0 = blockIdx.x * 16;

#pragma unroll
    for (int it = 0; it < 8; ++it) {
        const int idx = tid + it * 256;
        s_hm[idx >> 7][idx & 127] = hin[r0 * Dm + idx];
    }
    __syncthreads();

    // phase A: hsum[r][j] = sum_{d=0..4, i>=d} gelu(ps[j] + pn[i-d][j] + b1[j])
#pragma unroll
    for (int it = 0; it < 8; ++it) {
        const int idx = tid + it * 256;
        const int r = idx >> 7, j = idx & 127;
        const int row = r0 + r;
        const int i = row & (NCH - 1);
        const float ps = g_proj[row * Hm + j];
        const float b1 = mb1[j];
        float a = 0.f;
#pragma unroll
        for (int dd = 0; dd < 5; ++dd) {
            if (i >= dd) {
                const float pn = g_proj[(row - dd) * Hm + 128 + j];
                a += gelu_f(ps + pn + b1);
            }
        }
        s_hs[r][j] = a;
    }
    __syncthreads();

    const int hf = tid >> 7, j = tid & 127;
    const int rb = hf * 8;

    // phase B: agg = hsum @ msg_w2 / count + b2
    {
        float acc[8];
#pragma unroll
        for (int r = 0; r < 8; ++r) acc[r] = 0.f;
#pragma unroll 4
        for (int kk = 0; kk < Dm; ++kk) {
            const float w = mw2[kk * Dm + j];
#pragma unroll
            for (int r = 0; r < 8; ++r) acc[r] += s_hs[rb + r][kk] * w;
        }
        const float b2 = mb2[j];
#pragma unroll
        for (int r = 0; r < 8; ++r) {
            const int i = (r0 + rb + r) & (NCH - 1);
            const float cnt = (float)((i + 1) < 5 ? (i + 1) : 5);
            s_ag[rb + r][j] = acc[r] / cnt + b2;
        }
    }
    __syncthreads();

    // phase C: uh = gelu([hmsg, agg] @ upd_w1 + ub1)
    {
        float acc[8];
        const float bb = ub1[j];
#pragma unroll
        for (int r = 0; r < 8; ++r) acc[r] = bb;
#pragma unroll 4
        for (int dd = 0; dd < Dm; ++dd) {
            const float w = uw1[dd * Dm + j];
#pragma unroll
            for (int r = 0; r < 8; ++r) acc[r] += s_hm[rb + r][dd] * w;
        }
#pragma unroll 4
        for (int dd = 0; dd < Dm; ++dd) {
            const float w = uw1[(dd + 128) * Dm + j];
#pragma unroll
            for (int r = 0; r < 8; ++r) acc[r] += s_ag[rb + r][dd] * w;
        }
#pragma unroll
        for (int r = 0; r < 8; ++r) s_uh[rb + r][j] = gelu_f(acc[r]);
    }
    __syncthreads();

    // phase D: new = hmsg + uh @ upd_w2 + ub2  (store into s_hs)
    {
        float acc[8];
        const float bb = ub2[j];
#pragma unroll
        for (int r = 0; r < 8; ++r) acc[r] = bb;
#pragma unroll 4
        for (int kk = 0; kk < Dm; ++kk) {
            const float w = uw2[kk * Dm + j];
#pragma unroll
            for (int r = 0; r < 8; ++r) acc[r] += s_uh[rb + r][kk] * w;
        }
#pragma unroll
        for (int r = 0; r < 8; ++r) s_hs[rb + r][j] = s_hm[rb + r][j] + acc[r];
    }
    __syncthreads();

    // phase E: LN per row (8 warps x 2 rows)
    const int wq = tid >> 5, lane = tid & 31;
#pragma unroll
    for (int rr = 0; rr < 2; ++rr) {
        const int r = wq * 2 + rr;
        const float4 v = *(const float4*)&s_hs[r][lane * 4];
        const float mu = wsum(v.x + v.y + v.z + v.w) * (1.0f / Dm);
        const float a0 = v.x - mu, a1 = v.y - mu, a2 = v.z - mu, a3 = v.w - mu;
        const float var = wsum(a0 * a0 + a1 * a1 + a2 * a2 + a3 * a3) * (1.0f / Dm);
        const float rs = rsqrtf(var + EPSf);
        const int dd = lane * 4;
        float4 o;
        o.x = a0 * rs * lg[dd + 0] + lb[dd + 0];
        o.y = a1 * rs * lg[dd + 1] + lb[dd + 1];
        o.z = a2 * rs * lg[dd + 2] + lb[dd + 2];
        o.w = a3 * rs * lg[dd + 3] + lb[dd + 3];
        *(float4*)&hout[(r0 + r) * Dm + dd] = o;
    }
}

// ============================================================
// K4: bc = hmsg_final @ bc_w + bc_b  (hmsg_final lives in g_hB)
// ============================================================
__global__ __launch_bounds__(256) void k_bc(
    const float* __restrict__ w, const float* __restrict__ b)
{
    __shared__ float s_r[32][Dm];
    const int tid = threadIdx.x;
    const int r0 = blockIdx.x * 32;
#pragma unroll
    for (int it = 0; it < 16; ++it) {
        const int idx = tid + it * 256;
        s_r[idx >> 7][idx & 127] = g_hB[r0 * Dm + idx];
    }
    __syncthreads();
    const int hf = tid >> 7, j = tid & 127;
    const int rb = hf * 16;
    float acc[16];
    const float bb = b[j];
#pragma unroll
    for (int r = 0; r < 16; ++r) acc[r] = bb;
#pragma unroll 4
    for (int d = 0; d < Dm; ++d) {
        const float wv = w[d * Dm + j];
#pragma unroll
        for (int r = 0; r < 16; ++r) acc[r] += s_r[rb + r][d] * wv;
    }
#pragma unroll
    for (int r = 0; r < 16; ++r) g_bcb[(r0 + rb + r) * Dm + j] = acc[r];
}

// ============================================================
// K5: logits = LN(local + bc) @ head_w
// 32 tokens / block
// ============================================================
__global__ __launch_bounds__(256) void k_head(
    const float* __restrict__ lg, const float* __restrict__ lb,
    const float* __restrict__ hw, float* __restrict__ out)
{
    __shared__ float s_xln[32][Dm];
    const int tid = threadIdx.x;
    const int wq = tid >> 5, lane = tid & 31;
    const int gt0 = blockIdx.x * 32;

#pragma unroll
    for (int tt = 0; tt < 4; ++tt) {
        const int tl = wq * 4 + tt;
        const int gt = gt0 + tl;
        const int gc = gt >> 3;
        const float4 lv = *(const float4*)&g_local[gt * Dm + lane * 4];
        const float4 bv = *(const float4*)&g_bcb[gc * Dm + lane * 4];
        float h0 = lv.x + bv.x, h1 = lv.y + bv.y, h2 = lv.z + bv.z, h3 = lv.w + bv.w;
        const float mu = wsum(h0 + h1 + h2 + h3) * (1.0f / Dm);
        const float a0 = h0 - mu, a1 = h1 - mu, a2 = h2 - mu, a3 = h3 - mu;
        const float var = wsum(a0 * a0 + a1 * a1 + a2 * a2 + a3 * a3) * (1.0f / Dm);
        const float rs = rsqrtf(var + EPSf);
        const int dd = lane * 4;
        s_xln[tl][dd + 0] = a0 * rs * lg[dd + 0] + lb[dd + 0];
        s_xln[tl][dd + 1] = a1 * rs * lg[dd + 1] + lb[dd + 1];
        s_xln[tl][dd + 2] = a2 * rs * lg[dd + 2] + lb[dd + 2];
        s_xln[tl][dd + 3] = a3 * rs * lg[dd + 3] + lb[dd + 3];
    }
    __syncthreads();

    const int k = tid;
    float acc[32];
#pragma unroll
    for (int t = 0; t < 32; ++t) acc[t] = 0.f;
#pragma unroll 4
    for (int d = 0; d < Dm; ++d) {
        const float w = hw[d * Hm + k];
#pragma unroll
        for (int t = 0; t < 32; ++t) acc[t] += s_xln[t][d] * w;
    }
#pragma unroll
    for (int t = 0; t < 32; ++t) out[(gt0 + t) * Hm + k] = acc[t];
}

// ============================================================
extern "C" void kernel_launch(void* const* d_in, const int* in_sizes, int n_in,
                              void* d_out, int out_size) {
    const int*   x      = (const int*)  d_in[0];
    const float* emb    = (const float*)d_in[1];
    const float* pos    = (const float*)d_in[2];
    const float* lw1    = (const float*)d_in[3];
    const float* lb1    = (const float*)d_in[4];
    const float* lw2    = (const float*)d_in[5];
    const float* lb2    = (const float*)d_in[6];
    const float* lln_g  = (const float*)d_in[7];
    const float* lln_b  = (const float*)d_in[8];
    const float* pool_w = (const float*)d_in[9];
    const float* pool_b = (const float*)d_in[10];
    const float* msg_w1 = (const float*)d_in[11];
    const float* msg_b1 = (const float*)d_in[12];
    const float* msg_w2 = (const float*)d_in[13];
    const float* msg_b2 = (const float*)d_in[14];
    const float* upd_w1 = (const float*)d_in[15];
    const float* upd_b1 = (const float*)d_in[16];
    const float* upd_w2 = (const float*)d_in[17];
    const float* upd_b2 = (const float*)d_in[18];
    const float* mln_g  = (const float*)d_in[19];
    const float* mln_b  = (const float*)d_in[20];
    const float* bc_w   = (const float*)d_in[21];
    const float* bc_b   = (const float*)d_in[22];
    const float* fln_g  = (const float*)d_in[23];
    const float* fln_b  = (const float*)d_in[24];
    const float* head_w = (const float*)d_in[25];
    float* out = (float*)d_out;

    k_local<<<NTOK / 32, 256>>>(x, emb, pos, lw1, lb1, lw2, lb2, lln_g, lln_b);
    k_pool<<<ROWS / 32, 256>>>(pool_w, pool_b);

    // rounds: A->B, B->A, A->B  (final state in g_hB)
    for (int r = 0; r < 3; ++r) {
        const int useA = (r % 2 == 0) ? 1 : 0;
        k_proj<<<ROWS / 32, 256>>>(useA, msg_w1);
        k_msg<<<ROWS / 16, 256>>>(useA, msg_b1, msg_w2, msg_b2,
                                  upd_w1, upd_b1, upd_w2, upd_b2, mln_g, mln_b);
    }

    k_bc<<<ROWS / 32, 256>>>(bc_w, bc_b);
    k_head<<<NTOK / 32, 256>>>(fln_g, fln_b, head_w, out);
}

// round 2
// speedup vs baseline: 1.3067x; 1.3067x over previous
#include <cuda_runtime.h>

#define Dm 128
#define Hm 256
#define ROWS 16384   /* 16 * 1024 chunks */
#define NTOK 131072  /* 16 * 8192 tokens */
#define EPSf 1e-5f

typedef unsigned long long u64;

// ---- scratch (device globals; no allocation) ----
__device__ float g_local[NTOK * Dm];   // 64 MB
__device__ float g_hA[ROWS * Dm];      // 8 MB
__device__ float g_hB[ROWS * Dm];      // 8 MB
__device__ float g_proj[ROWS * Hm];    // 16 MB  [row][0:128]=self, [128:256]=nbr
__device__ float g_bcb[ROWS * Dm];     // 8 MB

// ---- packed f32x2 helpers ----
__device__ __forceinline__ u64 pk2(float x, float y) {
    u64 r; asm("mov.b64 %0, {%1, %2};" : "=l"(r) : "f"(x), "f"(y)); return r;
}
__device__ __forceinline__ u64 dup_f(float a) {
    u64 r; asm("mov.b64 %0, {%1, %1};" : "=l"(r) : "f"(a)); return r;
}
__device__ __forceinline__ void fma2(u64& d, u64 a, u64 b) {
    asm("fma.rn.f32x2 %0, %1, %2, %0;" : "+l"(d) : "l"(a), "l"(b));
}
__device__ __forceinline__ float2 u2f(u64 v) {
    float2 r; asm("mov.b64 {%0, %1}, %2;" : "=f"(r.x), "=f"(r.y) : "l"(v)); return r;
}

__device__ __forceinline__ float wsum(float v) {
#pragma unroll
    for (int o = 16; o; o >>= 1) v += __shfl_xor_sync(0xffffffffu, v, o);
    return v;
}
__device__ __forceinline__ float gelu_f(float x) { return x * normcdff(x); }

// warp LayerNorm of a 128-wide row held as float4 per lane
__device__ __forceinline__ float4 ln_f4(float4 h, const float* __restrict__ g,
                                        const float* __restrict__ b, int lane) {
    const float mu = wsum(h.x + h.y + h.z + h.w) * (1.0f / 128.0f);
    const float a0 = h.x - mu, a1 = h.y - mu, a2 = h.z - mu, a3 = h.w - mu;
    const float var = wsum(a0 * a0 + a1 * a1 + a2 * a2 + a3 * a3) * (1.0f / 128.0f);
    const float rs = rsqrtf(var + EPSf);
    const int dd = lane * 4;
    const float4 gg = *(const float4*)(g + dd);
    const float4 bb = *(const float4*)(b + dd);
    return make_float4(a0 * rs * gg.x + bb.x, a1 * rs * gg.y + bb.y,
                       a2 * rs * gg.z + bb.z, a3 * rs * gg.w + bb.w);
}

// ---- core register-tiled GEMM accumulate ----
// s: smem activations, RPT consecutive rows of stride KDIM (pre-offset to first row)
// W: weights pre-offset to this thread's first column; ldw = row stride of W
// acc[r][c]: fp32x2 accumulators, pair c covers cols (2c, 2c+1) rel. to W offset
template<int KDIM, int RPT, int NCP>
__device__ __forceinline__ void mm_acc(const float* __restrict__ s,
                                       const float* __restrict__ W, const int ldw,
                                       u64 acc[RPT][NCP]) {
#pragma unroll 2
    for (int d = 0; d < KDIM; d += 2) {
        u64 w0[NCP], w1[NCP];
#pragma unroll
        for (int c = 0; c < NCP; c += 2) {
            const ulonglong2 t0 = *(const ulonglong2*)(W + d * ldw + c * 2);
            const ulonglong2 t1 = *(const ulonglong2*)(W + (d + 1) * ldw + c * 2);
            w0[c] = t0.x; w0[c + 1] = t0.y;
            w1[c] = t1.x; w1[c + 1] = t1.y;
        }
#pragma unroll
        for (int r = 0; r < RPT; ++r) {
            const float2 a = *(const float2*)(s + r * KDIM + d);
            const u64 a0 = dup_f(a.x), a1 = dup_f(a.y);
#pragma unroll
            for (int c = 0; c < NCP; ++c) {
                fma2(acc[r][c], a0, w0[c]);
                fma2(acc[r][c], a1, w1[c]);
            }
        }
    }
}

// ============================================================
// K1: local = h + MLP2(LN(h)); h = emb[x] + pos[t%8]
// 64 tokens / block, 256 threads, dyn smem 96KB
// ============================================================
__global__ __launch_bounds__(256) void k_local(
    const int* __restrict__ x, const float* __restrict__ emb, const float* __restrict__ pos,
    const float* __restrict__ lw1, const float* __restrict__ lb1,
    const float* __restrict__ lw2, const float* __restrict__ lb2,
    const float* __restrict__ lng, const float* __restrict__ lnb)
{
    extern __shared__ float sm[];
    float* s_x = sm;               // 64*128
    float* s_h = sm + 64 * 128;    // 64*256
    const int tid = threadIdx.x, wq = tid >> 5, lane = tid & 31;
    const int gt0 = blockIdx.x * 64;

    // phase 1: LN per token
#pragma unroll
    for (int tt = 0; tt < 8; ++tt) {
        const int tl = wq * 8 + tt, gt = gt0 + tl;
        const int xt = __ldg(x + gt);
        const float4 e = *(const float4*)(emb + xt * Dm + lane * 4);
        const float4 p = *(const float4*)(pos + (gt & 7) * Dm + lane * 4);
        const float4 h = make_float4(e.x + p.x, e.y + p.y, e.z + p.z, e.w + p.w);
        *(float4*)(s_x + tl * Dm + lane * 4) = ln_f4(h, lng, lnb, lane);
    }
    __syncthreads();

    // phase 2: hid = gelu(xln @ lw1 + b1)  (64 x 256)
    {
        const int j0 = (tid & 31) * 8, rg = tid >> 5;
        u64 acc[8][4];
#pragma unroll
        for (int c = 0; c < 4; ++c) {
            const u64 bp = pk2(lb1[j0 + 2 * c], lb1[j0 + 2 * c + 1]);
#pragma unroll
            for (int r = 0; r < 8; ++r) acc[r][c] = bp;
        }
        mm_acc<128, 8, 4>(s_x + rg * 8 * 128, lw1 + j0, 256, acc);
#pragma unroll
        for (int r = 0; r < 8; ++r) {
            float o[8];
#pragma unroll
            for (int c = 0; c < 4; ++c) {
                const float2 v = u2f(acc[r][c]);
                o[2 * c] = gelu_f(v.x); o[2 * c + 1] = gelu_f(v.y);
            }
            float* dst = s_h + (rg * 8 + r) * 256 + j0;
            *(float4*)dst       = make_float4(o[0], o[1], o[2], o[3]);
            *(float4*)(dst + 4) = make_float4(o[4], o[5], o[6], o[7]);
        }
    }
    __syncthreads();

    // phase 3: out = h + hid @ lw2 + b2  (64 x 128)
    {
        const int j0 = (tid & 31) * 4, rg = tid >> 5;
        u64 acc[8][2];
#pragma unroll
        for (int c = 0; c < 2; ++c) {
            const u64 bp = pk2(lb2[j0 + 2 * c], lb2[j0 + 2 * c + 1]);
#pragma unroll
            for (int r = 0; r < 8; ++r) acc[r][c] = bp;
        }
        mm_acc<256, 8, 2>(s_h + rg * 8 * 256, lw2 + j0, 128, acc);
#pragma unroll
        for (int r = 0; r < 8; ++r) {
            const int gt = gt0 + rg * 8 + r;
            const int xt = __ldg(x + gt);
            const float4 e = *(const float4*)(emb + xt * Dm + j0);
            const float4 p = *(const float4*)(pos + (gt & 7) * Dm + j0);
            const float2 v0 = u2f(acc[r][0]), v1 = u2f(acc[r][1]);
            *(float4*)(g_local + gt * Dm + j0) =
                make_float4(e.x + p.x + v0.x, e.y + p.y + v0.y,
                            e.z + p.z + v1.x, e.w + p.w + v1.y);
        }
    }
}

// ============================================================
// K2: summ = mean(local over chunk) @ pool_w + pool_b -> g_hA
// 64 chunks / block
// ============================================================
__global__ __launch_bounds__(256) void k_pool(
    const float* __restrict__ pw, const float* __restrict__ pb)
{
    __shared__ float s_m[64 * 128];
    const int tid = threadIdx.x;
    const int gc0 = blockIdx.x * 64;
#pragma unroll
    for (int it = 0; it < 32; ++it) {
        const int idx = tid + it * 256;
        const int c = idx >> 7, dd = idx & 127;
        const float* src = g_local + ((gc0 + c) * 8) * Dm + dd;
        float s = 0.f;
#pragma unroll
        for (int j = 0; j < 8; ++j) s += src[j * Dm];
        s_m[c * 128 + dd] = s * 0.125f;
    }
    __syncthreads();
    const int j0 = (tid & 31) * 4, rg = tid >> 5;
    u64 acc[8][2];
#pragma unroll
    for (int c = 0; c < 2; ++c) {
        const u64 bp = pk2(pb[j0 + 2 * c], pb[j0 + 2 * c + 1]);
#pragma unroll
        for (int r = 0; r < 8; ++r) acc[r][c] = bp;
    }
    mm_acc<128, 8, 2>(s_m + rg * 8 * 128, pw + j0, 128, acc);
#pragma unroll
    for (int r = 0; r < 8; ++r) {
        const float2 v0 = u2f(acc[r][0]), v1 = u2f(acc[r][1]);
        *(float4*)(g_hA + (gc0 + rg * 8 + r) * Dm + j0) = make_float4(v0.x, v0.y, v1.x, v1.y);
    }
}

// ============================================================
// K3a: proj = [hmsg @ w1_self | hmsg @ w1_nbr]  (64 rows x 256)
// ============================================================
__global__ __launch_bounds__(256) void k_proj(int useA, const float* __restrict__ mw1)
{
    const float* __restrict__ hin = useA ? g_hA : g_hB;
    __shared__ float s_r[64 * 128];
    const int tid = threadIdx.x;
    const int r0 = blockIdx.x * 64;
#pragma unroll
    for (int it = 0; it < 32; ++it) {
        const int idx = tid + it * 256;
        s_r[idx] = hin[r0 * Dm + idx];
    }
    __syncthreads();
    const int j0 = (tid & 31) * 8, rg = tid >> 5;
    u64 acc[8][4];
#pragma unroll
    for (int r = 0; r < 8; ++r)
#pragma unroll
        for (int c = 0; c < 4; ++c) acc[r][c] = 0ull;
    const float* Wp = (j0 < 128) ? (mw1 + j0) : (mw1 + 128 * 128 + (j0 - 128));
    mm_acc<128, 8, 4>(s_r + rg * 8 * 128, Wp, 128, acc);
#pragma unroll
    for (int r = 0; r < 8; ++r) {
        float* dst = g_proj + (r0 + rg * 8 + r) * Hm + j0;
        const float2 v0 = u2f(acc[r][0]), v1 = u2f(acc[r][1]);
        const float2 v2 = u2f(acc[r][2]), v3 = u2f(acc[r][3]);
        *(float4*)dst       = make_float4(v0.x, v0.y, v1.x, v1.y);
        *(float4*)(dst + 4) = make_float4(v2.x, v2.y, v3.x, v3.y);
    }
}

// ============================================================
// K3b: gelu-sum -> agg -> upd MLP -> hmsg' = LN(hmsg + upd)
// 64 rows / block, dyn smem 96KB
// ============================================================
__global__ __launch_bounds__(256) void k_msg(
    int useA,
    const float* __restrict__ mb1, const float* __restrict__ mw2, const float* __restrict__ mb2,
    const float* __restrict__ uw1, const float* __restrict__ ub1,
    const float* __restrict__ uw2, const float* __restrict__ ub2,
    const float* __restrict__ lg, const float* __restrict__ lb)
{
    const float* __restrict__ hin = useA ? g_hA : g_hB;
    float* __restrict__ hout = useA ? g_hB : g_hA;
    extern __shared__ float sm[];
    float* s_hm = sm;              // 64*128 hmsg
    float* s_hs = sm + 8192;       // 64*128 gelu-sum, then uh
    float* s_ag = sm + 16384;      // 64*128 agg, then pre-LN result
    const int tid = threadIdx.x, wq = tid >> 5, lane = tid & 31;
    const int r0 = blockIdx.x * 64;

#pragma unroll
    for (int it = 0; it < 32; ++it) {
        const int idx = tid + it * 256;
        s_hm[idx] = hin[r0 * Dm + idx];
    }
    __syncthreads();

    // phase A: s_hs[r][j] = sum_{d=0..4, i>=d} gelu(ps[j] + pn[row-d][j] + b1[j])
#pragma unroll
    for (int it = 0; it < 32; ++it) {
        const int idx = tid + it * 256;
        const int r = idx >> 7, j = idx & 127;
        const int row = r0 + r;
        const int i = row & 1023;
        const float ps = g_proj[row * Hm + j];
        const float b1 = mb1[j];
        float a = 0.f;
#pragma unroll
        for (int dd = 0; dd < 5; ++dd) {
            if (i >= dd) a += gelu_f(ps + g_proj[(row - dd) * Hm + 128 + j] + b1);
        }
        s_hs[r * 128 + j] = a;
    }
    __syncthreads();

    const int j0 = (tid & 31) * 4, rg = tid >> 5;

    // phase B: agg = hsum @ msg_w2 / count + b2 -> s_ag
    {
        u64 acc[8][2];
#pragma unroll
        for (int r = 0; r < 8; ++r) { acc[r][0] = 0ull; acc[r][1] = 0ull; }
        mm_acc<128, 8, 2>(s_hs + rg * 8 * 128, mw2 + j0, 128, acc);
        const float4 b2 = *(const float4*)(mb2 + j0);
#pragma unroll
        for (int r = 0; r < 8; ++r) {
            const int i = (r0 + rg * 8 + r) & 1023;
            const float inv = 1.0f / ((i + 1) < 5 ? (float)(i + 1) : 5.0f);
            const float2 v0 = u2f(acc[r][0]), v1 = u2f(acc[r][1]);
            *(float4*)(s_ag + (rg * 8 + r) * 128 + j0) =
                make_float4(v0.x * inv + b2.x, v0.y * inv + b2.y,
                            v1.x * inv + b2.z, v1.y * inv + b2.w);
        }
    }
    __syncthreads();

    // phase C: uh = gelu([hmsg, agg] @ upd_w1 + ub1) -> s_hs
    {
        u64 acc[8][2];
#pragma unroll
        for (int c = 0; c < 2; ++c) {
            const u64 bp = pk2(ub1[j0 + 2 * c], ub1[j0 + 2 * c + 1]);
#pragma unroll
            for (int r = 0; r < 8; ++r) acc[r][c] = bp;
        }
        mm_acc<128, 8, 2>(s_hm + rg * 8 * 128, uw1 + j0, 128, acc);
        mm_acc<128, 8, 2>(s_ag + rg * 8 * 128, uw1 + 128 * 128 + j0, 128, acc);
#pragma unroll
        for (int r = 0; r < 8; ++r) {
            const float2 v0 = u2f(acc[r][0]), v1 = u2f(acc[r][1]);
            *(float4*)(s_hs + (rg * 8 + r) * 128 + j0) =
                make_float4(gelu_f(v0.x), gelu_f(v0.y), gelu_f(v1.x), gelu_f(v1.y));
        }
    }
    __syncthreads();

    // phase D: pre-LN = hmsg + uh @ upd_w2 + ub2 -> s_ag
    {
        u64 acc[8][2];
#pragma unroll
        for (int c = 0; c < 2; ++c) {
            const u64 bp = pk2(ub2[j0 + 2 * c], ub2[j0 + 2 * c + 1]);
#pragma unroll
            for (int r = 0; r < 8; ++r) acc[r][c] = bp;
        }
        mm_acc<128, 8, 2>(s_hs + rg * 8 * 128, uw2 + j0, 128, acc);
#pragma unroll
        for (int r = 0; r < 8; ++r) {
            const float2 v0 = u2f(acc[r][0]), v1 = u2f(acc[r][1]);
            const float4 hm = *(const float4*)(s_hm + (rg * 8 + r) * 128 + j0);
            *(float4*)(s_ag + (rg * 8 + r) * 128 + j0) =
                make_float4(hm.x + v0.x, hm.y + v0.y, hm.z + v1.x, hm.w + v1.y);
        }
    }
    __syncthreads();

    // phase E: LN per row
#pragma unroll
    for (int rr = 0; rr < 8; ++rr) {
        const int r = wq * 8 + rr;
        const float4 v = *(const float4*)(s_ag + r * 128 + lane * 4);
        *(float4*)(hout + (r0 + r) * Dm + lane * 4) = ln_f4(v, lg, lb, lane);
    }
}

// ============================================================
// K4: bc = hmsg_final @ bc_w + bc_b  (final state in g_hB)
// ============================================================
__global__ __launch_bounds__(256) void k_bc(
    const float* __restrict__ w, const float* __restrict__ b)
{
    __shared__ float s_r[64 * 128];
    const int tid = threadIdx.x;
    const int r0 = blockIdx.x * 64;
#pragma unroll
    for (int it = 0; it < 32; ++it) {
        const int idx = tid + it * 256;
        s_r[idx] = g_hB[r0 * Dm + idx];
    }
    __syncthreads();
    const int j0 = (tid & 31) * 4, rg = tid >> 5;
    u64 acc[8][2];
#pragma unroll
    for (int c = 0; c < 2; ++c) {
        const u64 bp = pk2(b[j0 + 2 * c], b[j0 + 2 * c + 1]);
#pragma unroll
        for (int r = 0; r < 8; ++r) acc[r][c] = bp;
    }
    mm_acc<128, 8, 2>(s_r + rg * 8 * 128, w + j0, 128, acc);
#pragma unroll
    for (int r = 0; r < 8; ++r) {
        const float2 v0 = u2f(acc[r][0]), v1 = u2f(acc[r][1]);
        *(float4*)(g_bcb + (r0 + rg * 8 + r) * Dm + j0) = make_float4(v0.x, v0.y, v1.x, v1.y);
    }
}

// ============================================================
// K5: logits = LN(local + bc) @ head_w  (64 tokens / block)
// ============================================================
__global__ __launch_bounds__(256) void k_head(
    const float* __restrict__ lg, const float* __restrict__ lb,
    const float* __restrict__ hw, float* __restrict__ out)
{
    __shared__ float s_x[64 * 128];
    const int tid = threadIdx.x, wq = tid >> 5, lane = tid & 31;
    const int gt0 = blockIdx.x * 64;

#pragma unroll
    for (int tt = 0; tt < 8; ++tt) {
        const int tl = wq * 8 + tt, gt = gt0 + tl;
        const float4 lv = *(const float4*)(g_local + gt * Dm + lane * 4);
        const float4 bv = *(const float4*)(g_bcb + (gt >> 3) * Dm + lane * 4);
        const float4 h = make_float4(lv.x + bv.x, lv.y + bv.y, lv.z + bv.z, lv.w + bv.w);
        *(float4*)(s_x + tl * 128 + lane * 4) = ln_f4(h, lg, lb, lane);
    }
    __syncthreads();

    const int j0 = (tid & 31) * 8, rg = tid >> 5;
    u64 acc[8][4];
#pragma unroll
    for (int r = 0; r < 8; ++r)
#pragma unroll
        for (int c = 0; c < 4; ++c) acc[r][c] = 0ull;
    mm_acc<128, 8, 4>(s_x + rg * 8 * 128, hw + j0, 256, acc);
#pragma unroll
    for (int r = 0; r < 8; ++r) {
        float* dst = out + (gt0 + rg * 8 + r) * Hm + j0;
        const float2 v0 = u2f(acc[r][0]), v1 = u2f(acc[r][1]);
        const float2 v2 = u2f(acc[r][2]), v3 = u2f(acc[r][3]);
        *(float4*)dst       = make_float4(v0.x, v0.y, v1.x, v1.y);
        *(float4*)(dst + 4) = make_float4(v2.x, v2.y, v3.x, v3.y);
    }
}

// ============================================================
extern "C" void kernel_launch(void* const* d_in, const int* in_sizes, int n_in,
                              void* d_out, int out_size) {
    const int*   x      = (const int*)  d_in[0];
    const float* emb    = (const float*)d_in[1];
    const float* pos    = (const float*)d_in[2];
    const float* lw1    = (const float*)d_in[3];
    const float* lb1    = (const float*)d_in[4];
    const float* lw2    = (const float*)d_in[5];
    const float* lb2    = (const float*)d_in[6];
    const float* lln_g  = (const float*)d_in[7];
    const float* lln_b  = (const float*)d_in[8];
    const float* pool_w = (const float*)d_in[9];
    const float* pool_b = (const float*)d_in[10];
    const float* msg_w1 = (const float*)d_in[11];
    const float* msg_b1 = (const float*)d_in[12];
    const float* msg_w2 = (const float*)d_in[13];
    const float* msg_b2 = (const float*)d_in[14];
    const float* upd_w1 = (const float*)d_in[15];
    const float* upd_b1 = (const float*)d_in[16];
    const float* upd_w2 = (const float*)d_in[17];
    const float* upd_b2 = (const float*)d_in[18];
    const float* mln_g  = (const float*)d_in[19];
    const float* mln_b  = (const float*)d_in[20];
    const float* bc_w   = (const float*)d_in[21];
    const float* bc_b   = (const float*)d_in[22];
    const float* fln_g  = (const float*)d_in[23];
    const float* fln_b  = (const float*)d_in[24];
    const float* head_w = (const float*)d_in[25];
    float* out = (float*)d_out;

    const int SMEM_LOCAL = 96 * 1024;
    const int SMEM_MSG   = 96 * 1024;
    cudaFuncSetAttribute(k_local, cudaFuncAttributeMaxDynamicSharedMemorySize, SMEM_LOCAL);
    cudaFuncSetAttribute(k_msg,   cudaFuncAttributeMaxDynamicSharedMemorySize, SMEM_MSG);

    k_local<<<NTOK / 64, 256, SMEM_LOCAL>>>(x, emb, pos, lw1, lb1, lw2, lb2, lln_g, lln_b);
    k_pool<<<ROWS / 64, 256>>>(pool_w, pool_b);

    // rounds: A->B, B->A, A->B  (final state in g_hB)
    for (int r = 0; r < 3; ++r) {
        const int useA = (r % 2 == 0) ? 1 : 0;
        k_proj<<<ROWS / 64, 256>>>(useA, msg_w1);
        k_msg<<<ROWS / 64, 256, SMEM_MSG>>>(useA, msg_b1, msg_w2, msg_b2,
                                            upd_w1, upd_b1, upd_w2, upd_b2, mln_g, mln_b);
    }

    k_bc<<<ROWS / 64, 256>>>(bc_w, bc_b);
    k_head<<<NTOK / 64, 256>>>(fln_g, fln_b, head_w, out);
}